// round 13
// baseline (speedup 1.0000x reference)
#include <cuda_runtime.h>

#define BB 256
#define HH 224
#define WW 224
#define HW (HH*WW)          // 50176
#define W4 (WW/4)           // 56
#define MPARTS 14
#define MROWS (HH/MPARTS)   // 16
#define TILE_ROWS 8
#define SRC_ROWS 9
#define NTILES (HH/TILE_ROWS)      // 28
#define ITEMS_A (BB*MPARTS)        // 3584
#define ITEMS_B (BB*NTILES)        // 7168

__device__ float g_partial[ITEMS_A];
__device__ unsigned g_workA, g_workB, g_arrive;

__global__ void init_counters() { g_workA = 0u; g_workB = 0u; g_arrive = 0u; }

// ---------------- color jitter for one pixel (streamlined v2) ----------------
// cm = (1-cf)*mg, omsf = 1-sf, hb = 1 + hue   (hoisted per image)
__device__ __forceinline__ void jitter_px(float& r, float& g, float& bl,
                                          float bf, float cf, float cm,
                                          float sf, float omsf, float hb)
{
    r = __saturatef(bf*r); g = __saturatef(bf*g); bl = __saturatef(bf*bl);
    r  = __saturatef(fmaf(cf, r,  cm));
    g  = __saturatef(fmaf(cf, g,  cm));
    bl = __saturatef(fmaf(cf, bl, cm));
    float gray = fmaf(0.299f, r, fmaf(0.587f, g, 0.114f*bl));
    float sg = omsf*gray;
    r  = __saturatef(fmaf(sf, r,  sg));
    g  = __saturatef(fmaf(sf, g,  sg));
    bl = __saturatef(fmaf(sf, bl, sg));
    float maxc = fmaxf(fmaxf(r,g),bl);
    float minc = fminf(fminf(r,g),bl);
    float v  = maxc;
    float cr = maxc - minc;
    float inv = __fdividef(1.0f, (cr == 0.0f) ? 1.0f : cr);
    float d    = (maxc == r) ? (g - bl) : (maxc == g) ? (bl - r) : (r - g);
    float base = (maxc == r) ? 0.0f     : (maxc == g) ? 2.0f     : 4.0f;
    float h = fmaf(fmaf(d, inv, base), 1.0f/6.0f, hb);   // h0/6 + 1 + hue
    h -= floorf(h);
    float h6 = h*6.0f;                      // in [0, 6)
    float kr = 5.0f + h6; kr = (kr >= 6.0f) ? (kr - 6.0f) : kr;
    float kg = 3.0f + h6; kg = (kg >= 6.0f) ? (kg - 6.0f) : kg;
    float kb = 1.0f + h6; kb = (kb >= 6.0f) ? (kb - 6.0f) : kb;
    r  = __saturatef(fmaf(-cr, __saturatef(fminf(kr, 4.0f - kr)), v));
    g  = __saturatef(fmaf(-cr, __saturatef(fminf(kg, 4.0f - kg)), v));
    bl = __saturatef(fmaf(-cr, __saturatef(fminf(kb, 4.0f - kb)), v));
}

// ---------------- Persistent fused kernel: mean phase -> barrier -> aug phase ----------------
__global__ void __launch_bounds__(256, 6) fused_kernel(
    const float* __restrict__ img,
    const float* __restrict__ u_jitter,
    const float* __restrict__ u_bright,
    const float* __restrict__ u_contrast,
    const float* __restrict__ u_sat,
    const float* __restrict__ u_hue,
    const float* __restrict__ u_crop,
    const float* __restrict__ u_scale,
    const float* __restrict__ u_top,
    const float* __restrict__ u_left,
    float* __restrict__ out,
    int nCTAs)
{
    __shared__ float sm[3][SRC_ROWS][WW];   // 24192 B
    __shared__ float red[8];
    __shared__ unsigned s_item;

    // ================= Phase A: per-image mean partials (work-stealing) =================
    for (;;) {
        if (threadIdx.x == 0) s_item = atomicAdd(&g_workA, 1u);
        __syncthreads();
        unsigned item = s_item;
        if (item >= ITEMS_A) break;
        int b    = item / MPARTS;
        int part = item - b*MPARTS;
        if (u_jitter[b] < 0.8f) {
            float bf = 1.0f + (2.0f*u_bright[b] - 1.0f)*0.2f;
            const float4* base = (const float4*)(img + (size_t)b*3*HW);
            int p0 = (part*MROWS*WW) >> 2;
            const int N4 = (MROWS*WW) >> 2;   // 896
            float sum = 0.0f;
            for (int i = threadIdx.x; i < N4; i += blockDim.x) {
                int p = p0 + i;
                float4 r4 = base[p];
                float4 g4 = base[(HW>>2)+p];
                float4 b4 = base[(2*(HW>>2))+p];
                #pragma unroll
                for (int j = 0; j < 4; j++) {
                    float r  = __saturatef(bf*((const float*)&r4)[j]);
                    float g  = __saturatef(bf*((const float*)&g4)[j]);
                    float bl = __saturatef(bf*((const float*)&b4)[j]);
                    sum += 0.299f*r + 0.587f*g + 0.114f*bl;
                }
            }
            #pragma unroll
            for (int s = 16; s > 0; s >>= 1) sum += __shfl_xor_sync(0xffffffffu, sum, s);
            if ((threadIdx.x & 31) == 0) red[threadIdx.x >> 5] = sum;
            __syncthreads();
            if (threadIdx.x < 8) {
                float v = red[threadIdx.x];
                #pragma unroll
                for (int s = 4; s > 0; s >>= 1) v += __shfl_xor_sync(0xffu, v, s);
                if (threadIdx.x == 0) g_partial[item] = v;
            }
        }
        __syncthreads();   // protect s_item / red reuse
    }

    // ================= device-wide barrier (all CTAs resident by construction) =========
    if (threadIdx.x == 0) {
        __threadfence();                       // release partials to device scope
        atomicAdd(&g_arrive, 1u);
        while (*(volatile unsigned*)&g_arrive < (unsigned)nCTAs) __nanosleep(128);
    }
    __syncthreads();

    // ================= Phase B: aug tiles (work-stealing) ===============================
    for (;;) {
        if (threadIdx.x == 0) s_item = atomicAdd(&g_workB, 1u);
        __syncthreads();
        unsigned t = s_item;
        if (t >= ITEMS_B) break;
        int b    = t / NTILES;
        int tile = t - b*NTILES;
        int ty0  = tile * TILE_ROWS;

        bool jit = (u_jitter[b] < 0.8f);
        bool crp = (u_crop[b]   < 0.5f);

        float bf = 1.0f + (2.0f*u_bright[b]   - 1.0f)*0.2f;
        float cf = 1.0f + (2.0f*u_contrast[b] - 1.0f)*0.2f;
        float sf = 1.0f + (2.0f*u_sat[b]      - 1.0f)*0.2f;
        float hb = 1.0f + (2.0f*u_hue[b] - 1.0f)*0.05f;     // 1 + hue
        float omsf = 1.0f - sf;
        float cm = 0.0f;
        if (jit) {
            float acc = 0.0f;
            #pragma unroll
            for (int k = 0; k < MPARTS; k++) acc += __ldcg(&g_partial[b*MPARTS+k]);
            cm = (1.0f - cf) * (acc * (1.0f/(float)HW));
        }

        const float* src = img + (size_t)b*3*HW;
        float*       dst = out + (size_t)b*3*HW;

        if (!crp) {
            // output = jittered (or raw) input rows, identity geometry
            const float4* s4 = (const float4*)src;
            float4*       d4 = (float4*)dst;
            if (!jit) {
                #pragma unroll
                for (int c = 0; c < 3; c++) {
                    int base = (c*HW + ty0*WW) >> 2;
                    for (int i = threadIdx.x; i < (TILE_ROWS*WW)>>2; i += blockDim.x)
                        d4[base+i] = s4[base+i];
                }
            } else {
                int base = (ty0*WW) >> 2;
                for (int i = threadIdx.x; i < (TILE_ROWS*WW)>>2; i += blockDim.x) {
                    int p = base + i;
                    float4 r4 = s4[p];
                    float4 g4 = s4[(HW>>2)+p];
                    float4 b4 = s4[(2*(HW>>2))+p];
                    #pragma unroll
                    for (int j = 0; j < 4; j++) {
                        float r  = ((const float*)&r4)[j];
                        float g  = ((const float*)&g4)[j];
                        float bl = ((const float*)&b4)[j];
                        jitter_px(r,g,bl, bf,cf,cm,sf,omsf,hb);
                        ((float*)&r4)[j] = r; ((float*)&g4)[j] = g; ((float*)&b4)[j] = bl;
                    }
                    d4[p] = r4;
                    d4[(HW>>2)+p] = g4;
                    d4[(2*(HW>>2))+p] = b4;
                }
            }
        } else {
            // ---- crop geometry: must match JAX fp32 op-for-op (floor decisions) ----
            float scale = __fadd_rn(0.85f, __fmul_rn((1.0f - 0.85f), u_scale[b]));
            float chf   = floorf(__fmul_rn(224.0f, scale));
            float cwf   = chf;   // H == W
            float hm    = __fadd_rn(__fsub_rn(224.0f, chf), 1.0f);
            float topf  = fminf(fmaxf(floorf(__fmul_rn(u_top[b],  hm)), 0.0f), 224.0f - chf);
            float leftf = fminf(fmaxf(floorf(__fmul_rn(u_left[b], hm)), 0.0f), 224.0f - cwf);

            const float inv224 = 1.0f/224.0f;

            float ys0 = fminf(fmaxf(topf + ((float)ty0 + 0.5f)*chf*inv224 - 0.5f, 0.0f), 223.0f);
            int ry0 = (int)floorf(ys0);

            // ---- phase 1: load + jitter SRC_ROWS x 224 slab into smem (float4) ----
            {
                const int NQ = (SRC_ROWS*WW) >> 2;   // 504
                const float4* s4 = (const float4*)src;
                for (int idx = threadIdx.x; idx < NQ; idx += blockDim.x) {
                    int row = idx / W4;
                    int c4  = idx - row*W4;
                    int srow = min(ry0 + row, HH-1);
                    int p = srow*W4 + c4;
                    float4 r4 = s4[p];
                    float4 g4 = s4[(HW>>2)+p];
                    float4 b4 = s4[(2*(HW>>2))+p];
                    if (jit) {
                        #pragma unroll
                        for (int j = 0; j < 4; j++) {
                            float r  = ((const float*)&r4)[j];
                            float g  = ((const float*)&g4)[j];
                            float bl = ((const float*)&b4)[j];
                            jitter_px(r,g,bl, bf,cf,cm,sf,omsf,hb);
                            ((float*)&r4)[j] = r; ((float*)&g4)[j] = g; ((float*)&b4)[j] = bl;
                        }
                    }
                    int col = c4*4;
                    *(float4*)&sm[0][row][col] = r4;
                    *(float4*)&sm[1][row][col] = g4;
                    *(float4*)&sm[2][row][col] = b4;
                }
            }
            __syncthreads();

            // ---- phase 2: bilinear sample TILE_ROWS x 224 output, 4 px per thread ----
            for (int idx = threadIdx.x; idx < TILE_ROWS*W4; idx += blockDim.x) {
                int ry = idx / W4;
                int c4 = idx - ry*W4;
                int oy = ty0 + ry;
                float ys = fminf(fmaxf(topf + ((float)oy + 0.5f)*chf*inv224 - 0.5f, 0.0f), 223.0f);
                float y0f = floorf(ys);
                float wy  = ys - y0f;
                int y0 = (int)y0f - ry0;
                int y1 = min((int)y0f + 1, HH-1) - ry0;

                int   x0[4], x1[4];
                float wx[4];
                #pragma unroll
                for (int j = 0; j < 4; j++) {
                    int ox = c4*4 + j;
                    float xs = fminf(fmaxf(leftf + ((float)ox + 0.5f)*cwf*inv224 - 0.5f, 0.0f), 223.0f);
                    float x0f = floorf(xs);
                    wx[j] = xs - x0f;
                    x0[j] = (int)x0f;
                    x1[j] = min(x0[j] + 1, WW-1);
                }

                float4* d4 = (float4*)dst;
                int po4 = oy*W4 + c4;
                #pragma unroll
                for (int c = 0; c < 3; c++) {
                    float4 o;
                    #pragma unroll
                    for (int j = 0; j < 4; j++) {
                        float a  = sm[c][y0][x0[j]], bq = sm[c][y0][x1[j]];
                        float cq = sm[c][y1][x0[j]], dq = sm[c][y1][x1[j]];
                        float row0 = fmaf(wx[j], bq - a,  a);
                        float row1 = fmaf(wx[j], dq - cq, cq);
                        ((float*)&o)[j] = fmaf(wy, row1 - row0, row0);
                    }
                    d4[c*(HW>>2) + po4] = o;
                }
            }
        }
        __syncthreads();   // protect sm / s_item reuse across stolen tiles
    }
}

extern "C" void kernel_launch(void* const* d_in, const int* in_sizes, int n_in,
                              void* d_out, int out_size)
{
    const float* img        = (const float*)d_in[0];
    const float* u_jitter   = (const float*)d_in[1];
    const float* u_bright   = (const float*)d_in[2];
    const float* u_contrast = (const float*)d_in[3];
    const float* u_sat      = (const float*)d_in[4];
    const float* u_hue      = (const float*)d_in[5];
    const float* u_crop     = (const float*)d_in[6];
    const float* u_scale    = (const float*)d_in[7];
    const float* u_top      = (const float*)d_in[8];
    const float* u_left     = (const float*)d_in[9];
    float* out = (float*)d_out;

    // Resident-grid sizing: guarantees every CTA is co-resident -> spin barrier is safe.
    int dev = 0;
    cudaGetDevice(&dev);
    int sms = 0;
    cudaDeviceGetAttribute(&sms, cudaDevAttrMultiProcessorCount, dev);
    if (sms <= 0) sms = 148;
    int nb = 0;
    cudaOccupancyMaxActiveBlocksPerMultiprocessor(&nb, fused_kernel, 256, 0);
    if (nb < 1) nb = 1;
    int grid = sms * nb;

    init_counters<<<1, 1>>>();
    fused_kernel<<<grid, 256>>>(img, u_jitter, u_bright, u_contrast, u_sat, u_hue,
                                u_crop, u_scale, u_top, u_left, out, grid);
}

// round 16
// speedup vs baseline: 1.4244x; 1.4244x over previous
#include <cuda_runtime.h>

#define BB 256
#define HH 224
#define WW 224
#define HW (HH*WW)          // 50176
#define W4 (WW/4)           // 56
#define PARTS 4
#define ROWS_PER_PART (HH/PARTS)   // 56
#define TILE_ROWS 8
#define SRC_ROWS 9
#define NTILES (HH/TILE_ROWS)      // 28

__device__ float g_partial[BB*PARTS];

// ---------------- Kernel 1: per-image mean of grayscale(clip(bf*img)) ----------------
__global__ void __launch_bounds__(256) mean_kernel(const float* __restrict__ img,
                                                   const float* __restrict__ u_jitter,
                                                   const float* __restrict__ u_bright)
{
    int b = blockIdx.y;
    int part = blockIdx.x;
    __shared__ float red[8];
    if (u_jitter[b] >= 0.8f) {           // mean unused for jitter-off images
#if __CUDA_ARCH__ >= 900
        cudaTriggerProgrammaticLaunchCompletion();
#endif
        return;
    }
    float bf = 1.0f + (2.0f*u_bright[b] - 1.0f)*0.2f;
    const float4* base = (const float4*)(img + (size_t)b*3*HW);
    int p0 = (part*ROWS_PER_PART*WW) >> 2;
    const int N4 = (ROWS_PER_PART*WW) >> 2;   // 3136
    float sum = 0.0f;
    for (int i = threadIdx.x; i < N4; i += blockDim.x) {
        int p = p0 + i;
        float4 r4 = base[p];
        float4 g4 = base[(HW>>2)+p];
        float4 b4 = base[(2*(HW>>2))+p];
        #pragma unroll
        for (int j = 0; j < 4; j++) {
            float r  = __saturatef(bf*((const float*)&r4)[j]);
            float g  = __saturatef(bf*((const float*)&g4)[j]);
            float bl = __saturatef(bf*((const float*)&b4)[j]);
            sum += 0.299f*r + 0.587f*g + 0.114f*bl;
        }
    }
    // warp + smem reduce
    #pragma unroll
    for (int s = 16; s > 0; s >>= 1) sum += __shfl_xor_sync(0xffffffffu, sum, s);
    if ((threadIdx.x & 31) == 0) red[threadIdx.x >> 5] = sum;
    __syncthreads();
    if (threadIdx.x < 8) {
        float v = red[threadIdx.x];
        #pragma unroll
        for (int s = 4; s > 0; s >>= 1) v += __shfl_xor_sync(0xffu, v, s);
        if (threadIdx.x == 0) {
            g_partial[b*PARTS+part] = v;
            __threadfence();             // make partial visible before trigger
        }
    }
    __syncthreads();
#if __CUDA_ARCH__ >= 900
    cudaTriggerProgrammaticLaunchCompletion();
#endif
}

// ---------------- color jitter for one pixel (streamlined v2) ----------------
// cm = (1-cf)*mg, omsf = 1-sf, hb = 1 + hue   (hoisted per image)
__device__ __forceinline__ void jitter_px(float& r, float& g, float& bl,
                                          float bf, float cf, float cm,
                                          float sf, float omsf, float hb)
{
    r = __saturatef(bf*r); g = __saturatef(bf*g); bl = __saturatef(bf*bl);
    r  = __saturatef(fmaf(cf, r,  cm));
    g  = __saturatef(fmaf(cf, g,  cm));
    bl = __saturatef(fmaf(cf, bl, cm));
    float gray = fmaf(0.299f, r, fmaf(0.587f, g, 0.114f*bl));
    float sg = omsf*gray;
    r  = __saturatef(fmaf(sf, r,  sg));
    g  = __saturatef(fmaf(sf, g,  sg));
    bl = __saturatef(fmaf(sf, bl, sg));
    float maxc = fmaxf(fmaxf(r,g),bl);
    float minc = fminf(fminf(r,g),bl);
    float v  = maxc;
    float cr = maxc - minc;
    float inv = __fdividef(1.0f, (cr == 0.0f) ? 1.0f : cr);
    float d    = (maxc == r) ? (g - bl) : (maxc == g) ? (bl - r) : (r - g);
    float base = (maxc == r) ? 0.0f     : (maxc == g) ? 2.0f     : 4.0f;
    float h = fmaf(fmaf(d, inv, base), 1.0f/6.0f, hb);   // h0/6 + 1 + hue
    h -= floorf(h);
    float h6 = h*6.0f;                      // in [0, 6)
    float kr = 5.0f + h6; kr = (kr >= 6.0f) ? (kr - 6.0f) : kr;
    float kg = 3.0f + h6; kg = (kg >= 6.0f) ? (kg - 6.0f) : kg;
    float kb = 1.0f + h6; kb = (kb >= 6.0f) ? (kb - 6.0f) : kb;
    r  = __saturatef(fmaf(-cr, __saturatef(fminf(kr, 4.0f - kr)), v));
    g  = __saturatef(fmaf(-cr, __saturatef(fminf(kg, 4.0f - kg)), v));
    bl = __saturatef(fmaf(-cr, __saturatef(fminf(kb, 4.0f - kb)), v));
}

// ---------------- crop-resize one tile (JIT templated) ----------------
template<bool JIT>
__device__ __forceinline__ void crop_tile(
    float (&sm)[3][SRC_ROWS][WW],
    const float* __restrict__ src, float* __restrict__ dst, int ty0,
    float usc, float utp, float ulf,
    float bf, float cf, float cm, float sf, float omsf, float hb)
{
    // ---- crop geometry: must match JAX fp32 op-for-op (floor decisions) ----
    float scale = __fadd_rn(0.85f, __fmul_rn((1.0f - 0.85f), usc));
    float chf   = floorf(__fmul_rn(224.0f, scale));
    float cwf   = chf;   // H == W
    float hm    = __fadd_rn(__fsub_rn(224.0f, chf), 1.0f);
    float topf  = fminf(fmaxf(floorf(__fmul_rn(utp, hm)), 0.0f), 224.0f - chf);
    float leftf = fminf(fmaxf(floorf(__fmul_rn(ulf, hm)), 0.0f), 224.0f - cwf);

    const float inv224 = 1.0f/224.0f;

    float ys0 = fminf(fmaxf(topf + ((float)ty0 + 0.5f)*chf*inv224 - 0.5f, 0.0f), 223.0f);
    int ry0 = (int)floorf(ys0);

    // ---- phase 1: load (+ jitter) SRC_ROWS x 224 slab into smem (float4) ----
    {
        const int NQ = (SRC_ROWS*WW) >> 2;   // 504
        const float4* s4 = (const float4*)src;
        for (int idx = threadIdx.x; idx < NQ; idx += blockDim.x) {
            int row = idx / W4;
            int c4  = idx - row*W4;
            int srow = min(ry0 + row, HH-1);
            int p = srow*W4 + c4;
            float4 r4 = s4[p];
            float4 g4 = s4[(HW>>2)+p];
            float4 b4 = s4[(2*(HW>>2))+p];
            if (JIT) {
                #pragma unroll
                for (int j = 0; j < 4; j++) {
                    float r  = ((const float*)&r4)[j];
                    float g  = ((const float*)&g4)[j];
                    float bl = ((const float*)&b4)[j];
                    jitter_px(r,g,bl, bf,cf,cm,sf,omsf,hb);
                    ((float*)&r4)[j] = r; ((float*)&g4)[j] = g; ((float*)&b4)[j] = bl;
                }
            }
            int col = c4*4;
            *(float4*)&sm[0][row][col] = r4;
            *(float4*)&sm[1][row][col] = g4;
            *(float4*)&sm[2][row][col] = b4;
        }
    }
    __syncthreads();

    // ---- phase 2: bilinear sample TILE_ROWS x 224 output, 4 px per thread ----
    for (int idx = threadIdx.x; idx < TILE_ROWS*W4; idx += blockDim.x) {
        int ry = idx / W4;
        int c4 = idx - ry*W4;
        int oy = ty0 + ry;
        float ys = fminf(fmaxf(topf + ((float)oy + 0.5f)*chf*inv224 - 0.5f, 0.0f), 223.0f);
        float y0f = floorf(ys);
        float wy  = ys - y0f;
        int y0 = (int)y0f - ry0;
        int y1 = min((int)y0f + 1, HH-1) - ry0;

        int   x0[4], x1[4];
        float wx[4];
        #pragma unroll
        for (int j = 0; j < 4; j++) {
            int ox = c4*4 + j;
            float xs = fminf(fmaxf(leftf + ((float)ox + 0.5f)*cwf*inv224 - 0.5f, 0.0f), 223.0f);
            float x0f = floorf(xs);
            wx[j] = xs - x0f;
            x0[j] = (int)x0f;
            x1[j] = min(x0[j] + 1, WW-1);
        }

        float4* d4 = (float4*)dst;
        int po4 = oy*W4 + c4;
        #pragma unroll
        for (int c = 0; c < 3; c++) {
            float4 o;
            #pragma unroll
            for (int j = 0; j < 4; j++) {
                float a  = sm[c][y0][x0[j]], bq = sm[c][y0][x1[j]];
                float cq = sm[c][y1][x0[j]], dq = sm[c][y1][x1[j]];
                float row0 = fmaf(wx[j], bq - a,  a);
                float row1 = fmaf(wx[j], dq - cq, cq);
                ((float*)&o)[j] = fmaf(wy, row1 - row0, row0);
            }
            d4[c*(HW>>2) + po4] = o;
        }
    }
}

// ---------------- Kernel 2: fused jitter + crop-resize (PDL secondary) ----------------
__global__ void __launch_bounds__(256, 6) aug_kernel(const float* __restrict__ img,
                                                  const float* __restrict__ u_jitter,
                                                  const float* __restrict__ u_bright,
                                                  const float* __restrict__ u_contrast,
                                                  const float* __restrict__ u_sat,
                                                  const float* __restrict__ u_hue,
                                                  const float* __restrict__ u_crop,
                                                  const float* __restrict__ u_scale,
                                                  const float* __restrict__ u_top,
                                                  const float* __restrict__ u_left,
                                                  float* __restrict__ out)
{
    __shared__ float sm[3][SRC_ROWS][WW];   // 24192 B

    int b   = blockIdx.y;
    int ty0 = blockIdx.x * TILE_ROWS;

    bool jit = (u_jitter[b] < 0.8f);
    bool crp = (u_crop[b]   < 0.5f);

    const float* src = img + (size_t)b*3*HW;
    float*       dst = out + (size_t)b*3*HW;

    // ========== jitter-OFF path: no dependency on mean_kernel — runs pre-sync ==========
    if (!jit) {
        if (!crp) {
            const float4* s4 = (const float4*)src;
            float4*       d4 = (float4*)dst;
            #pragma unroll
            for (int c = 0; c < 3; c++) {
                int base = (c*HW + ty0*WW) >> 2;
                for (int i = threadIdx.x; i < (TILE_ROWS*WW)>>2; i += blockDim.x)
                    d4[base+i] = s4[base+i];
            }
        } else {
            crop_tile<false>(sm, src, dst, ty0, u_scale[b], u_top[b], u_left[b],
                             0.f,0.f,0.f,0.f,0.f,0.f);
        }
        return;
    }

    // ========== jitter-ON path: needs mean partials ==========
#if __CUDA_ARCH__ >= 900
    cudaGridDependencySynchronize();
#endif

    float bf = 1.0f + (2.0f*u_bright[b]   - 1.0f)*0.2f;
    float cf = 1.0f + (2.0f*u_contrast[b] - 1.0f)*0.2f;
    float sf = 1.0f + (2.0f*u_sat[b]      - 1.0f)*0.2f;
    float hb = 1.0f + (2.0f*u_hue[b] - 1.0f)*0.05f;     // 1 + hue
    float omsf = 1.0f - sf;
    float acc = 0.0f;
    #pragma unroll
    for (int k = 0; k < PARTS; k++) acc += __ldcg(&g_partial[b*PARTS+k]);
    float cm = (1.0f - cf) * (acc * (1.0f/(float)HW));

    if (!crp) {
        const float4* s4 = (const float4*)src;
        float4*       d4 = (float4*)dst;
        int base = (ty0*WW) >> 2;
        for (int i = threadIdx.x; i < (TILE_ROWS*WW)>>2; i += blockDim.x) {
            int p = base + i;
            float4 r4 = s4[p];
            float4 g4 = s4[(HW>>2)+p];
            float4 b4 = s4[(2*(HW>>2))+p];
            #pragma unroll
            for (int j = 0; j < 4; j++) {
                float r  = ((const float*)&r4)[j];
                float g  = ((const float*)&g4)[j];
                float bl = ((const float*)&b4)[j];
                jitter_px(r,g,bl, bf,cf,cm,sf,omsf,hb);
                ((float*)&r4)[j] = r; ((float*)&g4)[j] = g; ((float*)&b4)[j] = bl;
            }
            d4[p] = r4;
            d4[(HW>>2)+p] = g4;
            d4[(2*(HW>>2))+p] = b4;
        }
    } else {
        crop_tile<true>(sm, src, dst, ty0, u_scale[b], u_top[b], u_left[b],
                        bf, cf, cm, sf, omsf, hb);
    }
}

extern "C" void kernel_launch(void* const* d_in, const int* in_sizes, int n_in,
                              void* d_out, int out_size)
{
    const float* img        = (const float*)d_in[0];
    const float* u_jitter   = (const float*)d_in[1];
    const float* u_bright   = (const float*)d_in[2];
    const float* u_contrast = (const float*)d_in[3];
    const float* u_sat      = (const float*)d_in[4];
    const float* u_hue      = (const float*)d_in[5];
    const float* u_crop     = (const float*)d_in[6];
    const float* u_scale    = (const float*)d_in[7];
    const float* u_top      = (const float*)d_in[8];
    const float* u_left     = (const float*)d_in[9];
    float* out = (float*)d_out;

    dim3 g1(PARTS, BB);
    mean_kernel<<<g1, 256>>>(img, u_jitter, u_bright);

    // aug: PDL secondary — launches while mean drains; jitter-on CTAs sync internally.
    cudaLaunchConfig_t cfg = {};
    cfg.gridDim  = dim3(NTILES, BB);
    cfg.blockDim = dim3(256, 1, 1);
    cfg.dynamicSmemBytes = 0;
    cfg.stream = 0;
    cudaLaunchAttribute attrs[1];
    attrs[0].id = cudaLaunchAttributeProgrammaticStreamSerialization;
    attrs[0].val.programmaticStreamSerializationAllowed = 1;
    cfg.attrs = attrs;
    cfg.numAttrs = 1;
    cudaLaunchKernelEx(&cfg, aug_kernel,
                       img, u_jitter, u_bright, u_contrast, u_sat, u_hue,
                       u_crop, u_scale, u_top, u_left, out);
}

// round 17
// speedup vs baseline: 1.5063x; 1.0575x over previous
#include <cuda_runtime.h>

#define BB 256
#define HH 224
#define WW 224
#define HW (HH*WW)          // 50176
#define W4 (WW/4)           // 56
#define PARTS 4
#define ROWS_PER_PART (HH/PARTS)   // 56
#define TILE_ROWS 8
#define SRC_ROWS 9
#define NTILES (HH/TILE_ROWS)      // 28

__device__ float g_partial[BB*PARTS];

// ---------------- Kernel 1: per-image mean of grayscale(clip(bf*img)) ----------------
__global__ void __launch_bounds__(256) mean_kernel(const float* __restrict__ img,
                                                   const float* __restrict__ u_jitter,
                                                   const float* __restrict__ u_bright)
{
    int b = blockIdx.y;
    int part = blockIdx.x;
    __shared__ float red[8];
    if (u_jitter[b] >= 0.8f) return;     // mean unused for jitter-off images
    float bf = 1.0f + (2.0f*u_bright[b] - 1.0f)*0.2f;
    const float4* base = (const float4*)(img + (size_t)b*3*HW);
    int p0 = (part*ROWS_PER_PART*WW) >> 2;
    const int N4 = (ROWS_PER_PART*WW) >> 2;   // 3136
    float sum = 0.0f;
    for (int i = threadIdx.x; i < N4; i += blockDim.x) {
        int p = p0 + i;
        float4 r4 = base[p];
        float4 g4 = base[(HW>>2)+p];
        float4 b4 = base[(2*(HW>>2))+p];
        #pragma unroll
        for (int j = 0; j < 4; j++) {
            float r  = __saturatef(bf*((const float*)&r4)[j]);
            float g  = __saturatef(bf*((const float*)&g4)[j]);
            float bl = __saturatef(bf*((const float*)&b4)[j]);
            sum += 0.299f*r + 0.587f*g + 0.114f*bl;
        }
    }
    // warp + smem reduce
    #pragma unroll
    for (int s = 16; s > 0; s >>= 1) sum += __shfl_xor_sync(0xffffffffu, sum, s);
    if ((threadIdx.x & 31) == 0) red[threadIdx.x >> 5] = sum;
    __syncthreads();
    if (threadIdx.x < 8) {
        float v = red[threadIdx.x];
        #pragma unroll
        for (int s = 4; s > 0; s >>= 1) v += __shfl_xor_sync(0xffu, v, s);
        if (threadIdx.x == 0) g_partial[b*PARTS+part] = v;
    }
}

// ---------------- color jitter for one pixel (streamlined v2) ----------------
// cm = (1-cf)*mg, omsf = 1-sf, hb = 1 + hue   (hoisted per image)
__device__ __forceinline__ void jitter_px(float& r, float& g, float& bl,
                                          float bf, float cf, float cm,
                                          float sf, float omsf, float hb)
{
    r = __saturatef(bf*r); g = __saturatef(bf*g); bl = __saturatef(bf*bl);
    r  = __saturatef(fmaf(cf, r,  cm));
    g  = __saturatef(fmaf(cf, g,  cm));
    bl = __saturatef(fmaf(cf, bl, cm));
    float gray = fmaf(0.299f, r, fmaf(0.587f, g, 0.114f*bl));
    float sg = omsf*gray;
    r  = __saturatef(fmaf(sf, r,  sg));
    g  = __saturatef(fmaf(sf, g,  sg));
    bl = __saturatef(fmaf(sf, bl, sg));
    float maxc = fmaxf(fmaxf(r,g),bl);
    float minc = fminf(fminf(r,g),bl);
    float v  = maxc;
    float cr = maxc - minc;
    float inv = __fdividef(1.0f, (cr == 0.0f) ? 1.0f : cr);
    float d    = (maxc == r) ? (g - bl) : (maxc == g) ? (bl - r) : (r - g);
    float base = (maxc == r) ? 0.0f     : (maxc == g) ? 2.0f     : 4.0f;
    float h = fmaf(fmaf(d, inv, base), 1.0f/6.0f, hb);   // h0/6 + 1 + hue
    h -= floorf(h);
    float h6 = h*6.0f;                      // in [0, 6)
    float kr = 5.0f + h6; kr = (kr >= 6.0f) ? (kr - 6.0f) : kr;
    float kg = 3.0f + h6; kg = (kg >= 6.0f) ? (kg - 6.0f) : kg;
    float kb = 1.0f + h6; kb = (kb >= 6.0f) ? (kb - 6.0f) : kb;
    r  = __saturatef(fmaf(-cr, __saturatef(fminf(kr, 4.0f - kr)), v));
    g  = __saturatef(fmaf(-cr, __saturatef(fminf(kg, 4.0f - kg)), v));
    bl = __saturatef(fmaf(-cr, __saturatef(fminf(kb, 4.0f - kb)), v));
}

// ---------------- Kernel 2: fused jitter + crop-resize ----------------
__global__ void __launch_bounds__(256, 6) aug_kernel(const float* __restrict__ img,
                                                  const float* __restrict__ u_jitter,
                                                  const float* __restrict__ u_bright,
                                                  const float* __restrict__ u_contrast,
                                                  const float* __restrict__ u_sat,
                                                  const float* __restrict__ u_hue,
                                                  const float* __restrict__ u_crop,
                                                  const float* __restrict__ u_scale,
                                                  const float* __restrict__ u_top,
                                                  const float* __restrict__ u_left,
                                                  float* __restrict__ out)
{
    __shared__ float sm[SRC_ROWS][WW][4];   // RGBA-interleaved, 32256 B

    int b   = blockIdx.y;
    int ty0 = blockIdx.x * TILE_ROWS;

    bool jit = (u_jitter[b] < 0.8f);
    bool crp = (u_crop[b]   < 0.5f);

    float bf = 1.0f + (2.0f*u_bright[b]   - 1.0f)*0.2f;
    float cf = 1.0f + (2.0f*u_contrast[b] - 1.0f)*0.2f;
    float sf = 1.0f + (2.0f*u_sat[b]      - 1.0f)*0.2f;
    float hb = 1.0f + (2.0f*u_hue[b] - 1.0f)*0.05f;     // 1 + hue
    float omsf = 1.0f - sf;
    float cm = 0.0f;
    if (jit) {
        float acc = 0.0f;
        #pragma unroll
        for (int k = 0; k < PARTS; k++) acc += g_partial[b*PARTS+k];
        cm = (1.0f - cf) * (acc * (1.0f/(float)HW));
    }

    const float* src = img + (size_t)b*3*HW;
    float*       dst = out + (size_t)b*3*HW;

    if (!crp) {
        // output = jittered (or raw) input rows, identity geometry
        const float4* s4 = (const float4*)src;
        float4*       d4 = (float4*)dst;
        if (!jit) {
            #pragma unroll
            for (int c = 0; c < 3; c++) {
                int base = (c*HW + ty0*WW) >> 2;
                for (int i = threadIdx.x; i < (TILE_ROWS*WW)>>2; i += blockDim.x)
                    d4[base+i] = s4[base+i];
            }
        } else {
            int base = (ty0*WW) >> 2;
            for (int i = threadIdx.x; i < (TILE_ROWS*WW)>>2; i += blockDim.x) {
                int p = base + i;
                float4 r4 = s4[p];
                float4 g4 = s4[(HW>>2)+p];
                float4 b4 = s4[(2*(HW>>2))+p];
                #pragma unroll
                for (int j = 0; j < 4; j++) {
                    float r  = ((const float*)&r4)[j];
                    float g  = ((const float*)&g4)[j];
                    float bl = ((const float*)&b4)[j];
                    jitter_px(r,g,bl, bf,cf,cm,sf,omsf,hb);
                    ((float*)&r4)[j] = r; ((float*)&g4)[j] = g; ((float*)&b4)[j] = bl;
                }
                d4[p] = r4;
                d4[(HW>>2)+p] = g4;
                d4[(2*(HW>>2))+p] = b4;
            }
        }
        return;
    }

    // ---- crop geometry: must match JAX fp32 op-for-op (floor decisions) ----
    float scale = __fadd_rn(0.85f, __fmul_rn((1.0f - 0.85f), u_scale[b]));
    float chf   = floorf(__fmul_rn(224.0f, scale));
    float cwf   = chf;   // H == W
    float hm    = __fadd_rn(__fsub_rn(224.0f, chf), 1.0f);
    float topf  = fminf(fmaxf(floorf(__fmul_rn(u_top[b],  hm)), 0.0f), 224.0f - chf);
    float leftf = fminf(fmaxf(floorf(__fmul_rn(u_left[b], hm)), 0.0f), 224.0f - cwf);

    const float inv224 = 1.0f/224.0f;

    // source row window for this tile (ys monotone in y; same formula as loop below)
    float ys0 = fminf(fmaxf(topf + ((float)ty0 + 0.5f)*chf*inv224 - 0.5f, 0.0f), 223.0f);
    int ry0 = (int)floorf(ys0);

    // ---- phase 1: load + jitter SRC_ROWS x 224 slab into RGBA smem (float4 loads) ----
    {
        const int NQ = (SRC_ROWS*WW) >> 2;   // 504
        const float4* s4 = (const float4*)src;
        for (int idx = threadIdx.x; idx < NQ; idx += blockDim.x) {
            int row = idx / W4;
            int c4  = idx - row*W4;
            int srow = min(ry0 + row, HH-1);
            int p = srow*W4 + c4;
            float4 r4 = s4[p];
            float4 g4 = s4[(HW>>2)+p];
            float4 b4 = s4[(2*(HW>>2))+p];
            int col = c4*4;
            #pragma unroll
            for (int j = 0; j < 4; j++) {
                float r  = ((const float*)&r4)[j];
                float g  = ((const float*)&g4)[j];
                float bl = ((const float*)&b4)[j];
                if (jit) jitter_px(r,g,bl, bf,cf,cm,sf,omsf,hb);
                *(float4*)&sm[row][col+j][0] = make_float4(r, g, bl, 0.0f);
            }
        }
    }
    __syncthreads();

    // ---- phase 2: bilinear sample; thread owns 4 SPREAD pixels (conflict-free LDS.128) ----
    for (int idx = threadIdx.x; idx < TILE_ROWS*W4; idx += blockDim.x) {
        int ry = idx / W4;
        int c4 = idx - ry*W4;
        int oy = ty0 + ry;
        float ys = fminf(fmaxf(topf + ((float)oy + 0.5f)*chf*inv224 - 0.5f, 0.0f), 223.0f);
        float y0f = floorf(ys);
        float wy  = ys - y0f;
        int y0 = (int)y0f - ry0;
        int y1 = min((int)y0f + 1, HH-1) - ry0;

        int po = oy*WW;
        #pragma unroll
        for (int j = 0; j < 4; j++) {
            int ox = c4 + j*W4;              // spread: adjacent lanes -> adjacent ox
            float xs = fminf(fmaxf(leftf + ((float)ox + 0.5f)*cwf*inv224 - 0.5f, 0.0f), 223.0f);
            float x0f = floorf(xs);
            float wx = xs - x0f;
            int x0 = (int)x0f;
            int x1 = min(x0 + 1, WW-1);

            float4 A  = *(const float4*)&sm[y0][x0][0];
            float4 Bq = *(const float4*)&sm[y0][x1][0];
            float4 Cq = *(const float4*)&sm[y1][x0][0];
            float4 Dq = *(const float4*)&sm[y1][x1][0];

            float r0x = fmaf(wx, Bq.x - A.x,  A.x);
            float r0y = fmaf(wx, Bq.y - A.y,  A.y);
            float r0z = fmaf(wx, Bq.z - A.z,  A.z);
            float r1x = fmaf(wx, Dq.x - Cq.x, Cq.x);
            float r1y = fmaf(wx, Dq.y - Cq.y, Cq.y);
            float r1z = fmaf(wx, Dq.z - Cq.z, Cq.z);

            dst[po + ox]        = fmaf(wy, r1x - r0x, r0x);
            dst[HW + po + ox]   = fmaf(wy, r1y - r0y, r0y);
            dst[2*HW + po + ox] = fmaf(wy, r1z - r0z, r0z);
        }
    }
}

extern "C" void kernel_launch(void* const* d_in, const int* in_sizes, int n_in,
                              void* d_out, int out_size)
{
    const float* img        = (const float*)d_in[0];
    const float* u_jitter   = (const float*)d_in[1];
    const float* u_bright   = (const float*)d_in[2];
    const float* u_contrast = (const float*)d_in[3];
    const float* u_sat      = (const float*)d_in[4];
    const float* u_hue      = (const float*)d_in[5];
    const float* u_crop     = (const float*)d_in[6];
    const float* u_scale    = (const float*)d_in[7];
    const float* u_top      = (const float*)d_in[8];
    const float* u_left     = (const float*)d_in[9];
    float* out = (float*)d_out;

    dim3 g1(PARTS, BB);
    mean_kernel<<<g1, 256>>>(img, u_jitter, u_bright);

    dim3 g2(NTILES, BB);
    aug_kernel<<<g2, 256>>>(img, u_jitter, u_bright, u_contrast, u_sat, u_hue,
                            u_crop, u_scale, u_top, u_left, out);
}